// round 13
// baseline (speedup 1.0000x reference)
#include <cuda_runtime.h>

#define FULLMASK 0xffffffffu
#define WS 256
#define NT 384
#define NB 96                           // batches per CTA
#define JB 4                            // batches per half-warp

// ---- smem layout (float offsets) ----
#define OFF_W1T  0                      // [64][256]  Whh1^T
#define OFF_W2T  (64 * WS)              // [128][256] Wih2^T | Whh2^T
#define OFF_WIH1 (OFF_W2T + 128 * WS)
#define OFF_CB1  (OFF_WIH1 + 256)
#define OFF_CB2  (OFF_CB1 + 256)
#define OFF_SM1  (OFF_CB2 + 256)        // mem1 buf: [96 batches][64 h]
#define SMEM_FLOATS (OFF_SM1 + NB * 64)
#define SMEM_BYTES  (SMEM_FLOATS * 4)   // 224256 B

typedef unsigned long long u64;

static __device__ __forceinline__ u64 splat2(float x) {
    u64 d; asm("mov.b64 %0, {%1, %1};" : "=l"(d) : "f"(x)); return d;
}
static __device__ __forceinline__ float2 unpack2(u64 v) {
    float lo, hi; asm("mov.b64 {%0, %1}, %2;" : "=f"(lo), "=f"(hi) : "l"(v));
    return make_float2(lo, hi);
}
static __device__ __forceinline__ u64 fma2(u64 a, u64 b, u64 c) {
    u64 d; asm("fma.rn.f32x2 %0, %1, %2, %3;" : "=l"(d) : "l"(a), "l"(b), "l"(c));
    return d;
}

// Fused SLSTM pointwise, 5 EX2 + 2 RCP.
static __device__ __forceinline__ void cellpw(float Gi, float Gf, float Gg, float Go,
                                              float& syn, float mem, float& memout,
                                              float& spk, float thr) {
    float a = 1.0f + __expf(-Gi);
    float c = 1.0f + __expf(-Gf);
    float b = 1.0f + __expf(-2.0f * Gg);
    float ab = a * b;
    float r = __fdividef(1.0f, ab * c);
    float sn = (ab * syn + c * (2.0f - b)) * r;
    float p = 1.0f + __expf(-Go);
    float q = 1.0f + __expf(-2.0f * sn);
    float s = __fdividef(1.0f, p * q);
    float rst = (mem > thr) ? thr : 0.0f;
    float mn = s * (2.0f - q) - rst;
    syn = sn;
    memout = mn;
    spk = (mn > thr) ? 1.0f : 0.0f;
}

// Matvec, smem-resident source (half-warp-uniform broadcast LDS.128).
static __device__ __forceinline__ void gemm_smem(u64 (&acc)[4][JB][2],
                                                 const float* __restrict__ wbase,
                                                 const float* __restrict__ srcb,
                                                 int n0) {
#pragma unroll 2
    for (int h4 = 0; h4 < 16; ++h4) {
        float4 s0 = *(const float4*)(srcb + 0 * 64 + h4 * 4);
        float4 s1 = *(const float4*)(srcb + 1 * 64 + h4 * 4);
        float4 s2 = *(const float4*)(srcb + 2 * 64 + h4 * 4);
        float4 s3 = *(const float4*)(srcb + 3 * 64 + h4 * 4);
#pragma unroll
        for (int n = 0; n < 4; ++n) {
            const float* wr = wbase + (h4 * 4 + n) * WS + n0;
            ulonglong2 wg0 = *(const ulonglong2*)(wr);
            ulonglong2 wg1 = *(const ulonglong2*)(wr + 64);
            ulonglong2 wg2 = *(const ulonglong2*)(wr + 128);
            ulonglong2 wg3 = *(const ulonglong2*)(wr + 192);
#pragma unroll
            for (int j = 0; j < JB; ++j) {
                float4& sj = (j == 0) ? s0 : (j == 1) ? s1 : (j == 2) ? s2 : s3;
                float sv = (n == 0) ? sj.x : (n == 1) ? sj.y : (n == 2) ? sj.z : sj.w;
                u64 s = splat2(sv);
                acc[0][j][0] = fma2(s, wg0.x, acc[0][j][0]);
                acc[0][j][1] = fma2(s, wg0.y, acc[0][j][1]);
                acc[1][j][0] = fma2(s, wg1.x, acc[1][j][0]);
                acc[1][j][1] = fma2(s, wg1.y, acc[1][j][1]);
                acc[2][j][0] = fma2(s, wg2.x, acc[2][j][0]);
                acc[2][j][1] = fma2(s, wg2.y, acc[2][j][1]);
                acc[3][j][0] = fma2(s, wg3.x, acc[3][j][0]);
                acc[3][j][1] = fma2(s, wg3.y, acc[3][j][1]);
            }
        }
    }
}

// Matvec, register source broadcast via shfl.
static __device__ __forceinline__ void gemm_shfl(u64 (&acc)[4][JB][2],
                                                 const float* __restrict__ wbase,
                                                 const float (&src)[4][JB],
                                                 int srcbase, int n0) {
#pragma unroll 2
    for (int h4 = 0; h4 < 16; ++h4) {
#pragma unroll
        for (int n = 0; n < 4; ++n) {
            const float* wr = wbase + (h4 * 4 + n) * WS + n0;
            ulonglong2 wg0 = *(const ulonglong2*)(wr);
            ulonglong2 wg1 = *(const ulonglong2*)(wr + 64);
            ulonglong2 wg2 = *(const ulonglong2*)(wr + 128);
            ulonglong2 wg3 = *(const ulonglong2*)(wr + 192);
#pragma unroll
            for (int j = 0; j < JB; ++j) {
                u64 s = splat2(__shfl_sync(FULLMASK, src[n][j], srcbase + h4));
                acc[0][j][0] = fma2(s, wg0.x, acc[0][j][0]);
                acc[0][j][1] = fma2(s, wg0.y, acc[0][j][1]);
                acc[1][j][0] = fma2(s, wg1.x, acc[1][j][0]);
                acc[1][j][1] = fma2(s, wg1.y, acc[1][j][1]);
                acc[2][j][0] = fma2(s, wg2.x, acc[2][j][0]);
                acc[2][j][1] = fma2(s, wg2.y, acc[2][j][1]);
                acc[3][j][0] = fma2(s, wg3.x, acc[3][j][0]);
                acc[3][j][1] = fma2(s, wg3.y, acc[3][j][1]);
            }
        }
    }
}

__global__ void __launch_bounds__(NT, 1)
snn_kernel(const float* __restrict__ x,
           const float* __restrict__ Wih1, const float* __restrict__ Whh1,
           const float* __restrict__ bih1, const float* __restrict__ bhh1,
           const float* __restrict__ thr1p,
           const float* __restrict__ Wih2, const float* __restrict__ Whh2,
           const float* __restrict__ bih2, const float* __restrict__ bhh2,
           const float* __restrict__ thr2p,
           const float* __restrict__ Wout, const float* __restrict__ bout,
           float* __restrict__ out, int Btot) {
    extern __shared__ float sm[];
    const int tid  = threadIdx.x;
    const int lane = tid & 31;
    const int w    = tid >> 5;
    const int hl   = lane & 15;
    const int bg   = lane >> 4;
    const int n0   = hl << 2;
    const int srcbase = bg << 4;
    const int bl   = w * 8 + bg * JB;
    const int cta_b0 = blockIdx.x * NB;

    for (int i = tid; i < 256 * 64; i += NT) {
        int r = i >> 6, h = i & 63;
        sm[OFF_W1T + h * WS + r]        = Whh1[i];
        sm[OFF_W2T + h * WS + r]        = Wih2[i];
        sm[OFF_W2T + (64 + h) * WS + r] = Whh2[i];
    }
    if (tid < 256) {
        sm[OFF_WIH1 + tid] = Wih1[tid];
        sm[OFF_CB1 + tid]  = bih1[tid] + bhh1[tid];
        sm[OFF_CB2 + tid]  = bih2[tid] + bhh2[tid];
    }
    for (int i = tid; i < NB * 64; i += NT) sm[OFF_SM1 + i] = 0.0f;
    __syncthreads();

    const float thr1 = thr1p[0], thr2 = thr2p[0];
    float* m1b = sm + OFF_SM1 + bl * 64;   // this half-warp's [j][h]

    // register state: syn1, syn2, mem2, spk1 (mem1 lives in smem)
    float syn1[4][JB], syn2[4][JB], mem2[4][JB], spk1[4][JB];
#pragma unroll
    for (int n = 0; n < 4; ++n)
#pragma unroll
        for (int j = 0; j < JB; ++j)
            syn1[n][j] = syn2[n][j] = mem2[n][j] = spk1[n][j] = 0.0f;

    float oa[JB][2];
#pragma unroll
    for (int j = 0; j < JB; ++j) oa[j][0] = oa[j][1] = 0.0f;

    u64 acc[4][JB][2];

#pragma unroll 1
    for (int t = 0; t < 25; ++t) {
        if (t < 24) {
            // ---- layer 1 ----
#pragma unroll
            for (int g = 0; g < 4; ++g)
#pragma unroll
                for (int j = 0; j < JB; ++j) acc[g][j][0] = acc[g][j][1] = 0ull;
            gemm_smem(acc, sm + OFF_W1T, m1b, n0);
#pragma unroll
            for (int j = 0; j < JB; ++j) {
                int b = cta_b0 + bl + j;
                float xv = (b < Btot) ? __ldg(&x[b * 24 + t]) : 0.0f;
                float4 pm = *(const float4*)(m1b + j * 64 + n0);  // prev mem1
                float2 G[4][2];
#pragma unroll
                for (int g = 0; g < 4; ++g) {
                    G[g][0] = unpack2(acc[g][j][0]);
                    G[g][1] = unpack2(acc[g][j][1]);
                }
                float nm[4];
#pragma unroll
                for (int n = 0; n < 4; ++n) {
                    float Gi = ((n & 1) ? G[0][n >> 1].y : G[0][n >> 1].x)
                             + sm[OFF_CB1 + 0 * 64 + n0 + n]
                             + xv * sm[OFF_WIH1 + 0 * 64 + n0 + n];
                    float Gf = ((n & 1) ? G[1][n >> 1].y : G[1][n >> 1].x)
                             + sm[OFF_CB1 + 1 * 64 + n0 + n]
                             + xv * sm[OFF_WIH1 + 1 * 64 + n0 + n];
                    float Gg = ((n & 1) ? G[2][n >> 1].y : G[2][n >> 1].x)
                             + sm[OFF_CB1 + 2 * 64 + n0 + n]
                             + xv * sm[OFF_WIH1 + 2 * 64 + n0 + n];
                    float Go = ((n & 1) ? G[3][n >> 1].y : G[3][n >> 1].x)
                             + sm[OFF_CB1 + 3 * 64 + n0 + n]
                             + xv * sm[OFF_WIH1 + 3 * 64 + n0 + n];
                    float pmv = (n == 0) ? pm.x : (n == 1) ? pm.y : (n == 2) ? pm.z : pm.w;
                    cellpw(Gi, Gf, Gg, Go, syn1[n][j], pmv, nm[n], spk1[n][j], thr1);
                }
                *(float4*)(m1b + j * 64 + n0) = make_float4(nm[0], nm[1], nm[2], nm[3]);
            }
            __syncwarp();
        }
        // ---- layer 2 ----
#pragma unroll
        for (int g = 0; g < 4; ++g)
#pragma unroll
            for (int j = 0; j < JB; ++j) acc[g][j][0] = acc[g][j][1] = 0ull;
        gemm_shfl(acc, sm + OFF_W2T + 64 * WS, mem2, srcbase, n0);
        if (t < 24) gemm_shfl(acc, sm + OFF_W2T, spk1, srcbase, n0);
        else        gemm_smem(acc, sm + OFF_W2T, m1b, n0);

        float4 wo0 = __ldg((const float4*)(Wout + t * 64 + n0));
        float4 wo1 = __ldg((const float4*)(Wout + 1664 + t * 64 + n0));
#pragma unroll
        for (int j = 0; j < JB; ++j) {
            float2 G[4][2];
#pragma unroll
            for (int g = 0; g < 4; ++g) {
                G[g][0] = unpack2(acc[g][j][0]);
                G[g][1] = unpack2(acc[g][j][1]);
            }
#pragma unroll
            for (int n = 0; n < 4; ++n) {
                float Gi = ((n & 1) ? G[0][n >> 1].y : G[0][n >> 1].x)
                         + sm[OFF_CB2 + 0 * 64 + n0 + n];
                float Gf = ((n & 1) ? G[1][n >> 1].y : G[1][n >> 1].x)
                         + sm[OFF_CB2 + 1 * 64 + n0 + n];
                float Gg = ((n & 1) ? G[2][n >> 1].y : G[2][n >> 1].x)
                         + sm[OFF_CB2 + 2 * 64 + n0 + n];
                float Go = ((n & 1) ? G[3][n >> 1].y : G[3][n >> 1].x)
                         + sm[OFF_CB2 + 3 * 64 + n0 + n];
                float sp, nm;
                cellpw(Gi, Gf, Gg, Go, syn2[n][j], mem2[n][j], nm, sp, thr2);
                mem2[n][j] = nm;
                float w0n = (n == 0) ? wo0.x : (n == 1) ? wo0.y : (n == 2) ? wo0.z : wo0.w;
                float w1n = (n == 0) ? wo1.x : (n == 1) ? wo1.y : (n == 2) ? wo1.z : wo1.w;
                oa[j][0] += sp * w0n;
                oa[j][1] += sp * w1n;
            }
        }
    }

    // ---- final mem2 contribution ----
    {
        float4 wm0 = __ldg((const float4*)(Wout + 1600 + n0));
        float4 wm1 = __ldg((const float4*)(Wout + 1664 + 1600 + n0));
#pragma unroll
        for (int n = 0; n < 4; ++n) {
            float a0 = (n == 0) ? wm0.x : (n == 1) ? wm0.y : (n == 2) ? wm0.z : wm0.w;
            float a1 = (n == 0) ? wm1.x : (n == 1) ? wm1.y : (n == 2) ? wm1.z : wm1.w;
#pragma unroll
            for (int j = 0; j < JB; ++j) {
                oa[j][0] += mem2[n][j] * a0;
                oa[j][1] += mem2[n][j] * a1;
            }
        }
    }

#pragma unroll
    for (int j = 0; j < JB; ++j)
#pragma unroll
        for (int k = 0; k < 2; ++k) {
            float v = oa[j][k];
#pragma unroll
            for (int off = 8; off; off >>= 1)
                v += __shfl_xor_sync(FULLMASK, v, off);
            oa[j][k] = v;
        }

    if (hl < 2 * JB) {
        int j = hl >> 1, k = hl & 1;
        int b = cta_b0 + bl + j;
        if (b < Btot) out[b * 2 + k] = oa[j][k] + __ldg(&bout[k]);
    }
}

extern "C" void kernel_launch(void* const* d_in, const int* in_sizes, int n_in,
                              void* d_out, int out_size) {
    const float* x    = (const float*)d_in[0];
    const float* Wih1 = (const float*)d_in[1];
    const float* Whh1 = (const float*)d_in[2];
    const float* bih1 = (const float*)d_in[3];
    const float* bhh1 = (const float*)d_in[4];
    const float* thr1 = (const float*)d_in[5];
    const float* Wih2 = (const float*)d_in[6];
    const float* Whh2 = (const float*)d_in[7];
    const float* bih2 = (const float*)d_in[8];
    const float* bhh2 = (const float*)d_in[9];
    const float* thr2 = (const float*)d_in[10];
    const float* Wout = (const float*)d_in[11];
    const float* bout = (const float*)d_in[12];
    float* out = (float*)d_out;

    int B = in_sizes[0] / 24;  // 65536
    int grid = (B + NB - 1) / NB;

    cudaFuncSetAttribute(snn_kernel,
                         cudaFuncAttributeMaxDynamicSharedMemorySize,
                         SMEM_BYTES);

    snn_kernel<<<grid, NT, SMEM_BYTES>>>(
        x, Wih1, Whh1, bih1, bhh1, thr1,
        Wih2, Whh2, bih2, bhh2, thr2, Wout, bout, out, B);
}

// round 16
// speedup vs baseline: 1.1749x; 1.1749x over previous
#include <cuda_runtime.h>

#define FULLMASK 0xffffffffu
#define WSTRIDE 258
#define NT 256

// ---- smem layout (float offsets) ----
#define OFF_W1T  0                      // [64][258]  Whh1^T
#define OFF_W2T  (64 * WSTRIDE)         // [128][258] rows 0..63 Wih2^T, 64..127 Whh2^T
#define OFF_WIH1 (OFF_W2T + 128 * WSTRIDE)
#define OFF_CB1  (OFF_WIH1 + 256)
#define OFF_CB2  (OFF_CB1 + 256)
#define OFF_WOUT (OFF_CB2 + 256)        // [2][1664]
#define OFF_XS   (OFF_WOUT + 3328)      // [64][24]
#define SMEM_FLOATS (OFF_XS + 64 * 24)
#define SMEM_BYTES  (SMEM_FLOATS * 4)   // 220672 B

typedef unsigned long long u64;

static __device__ __forceinline__ u64 splat2(float x) {
    u64 d; asm("mov.b64 %0, {%1, %1};" : "=l"(d) : "f"(x)); return d;
}
static __device__ __forceinline__ float2 unpack2(u64 v) {
    float lo, hi; asm("mov.b64 {%0, %1}, %2;" : "=f"(lo), "=f"(hi) : "l"(v));
    return make_float2(lo, hi);
}
static __device__ __forceinline__ u64 fma2(u64 a, u64 b, u64 c) {
    u64 d; asm("fma.rn.f32x2 %0, %1, %2, %3;" : "=l"(d) : "l"(a), "l"(b), "l"(c));
    return d;
}
static __device__ __forceinline__ u64 add2(u64 a, u64 b) {
    u64 d; asm("add.rn.f32x2 %0, %1, %2;" : "=l"(d) : "l"(a), "l"(b));
    return d;
}

// Fused SLSTM pointwise, 5 EX2 + 2 RCP (proven R4..R12, rel_err ~3e-8).
static __device__ __forceinline__ void cellpw(float Gi, float Gf, float Gg, float Go,
                                              float& syn, float& mem, float& spk,
                                              float thr) {
    float a = 1.0f + __expf(-Gi);
    float c = 1.0f + __expf(-Gf);
    float b = 1.0f + __expf(-2.0f * Gg);
    float ab = a * b;
    float r = __fdividef(1.0f, ab * c);
    float sn = (ab * syn + c * (2.0f - b)) * r;
    float p = 1.0f + __expf(-Go);
    float q = 1.0f + __expf(-2.0f * sn);
    float s = __fdividef(1.0f, p * q);
    float rst = (mem > thr) ? thr : 0.0f;
    float mn = s * (2.0f - q) - rst;
    syn = sn;
    mem = mn;
    spk = (mn > thr) ? 1.0f : 0.0f;
}

// Dense 64-row matvec (R3 layout): warp-uniform broadcast via shfl.
// Lane owns neuron pair n0=2*lane; src[n][j] = state of neuron 2*lane+n, batch j.
static __device__ __forceinline__ void gemm64(u64 (&acc)[4][8],
                                              const float* __restrict__ wbase,
                                              const float (&src)[2][8], int n0) {
#pragma unroll 2
    for (int h2 = 0; h2 < 32; ++h2) {
        const float* wr = wbase + (h2 * 2) * WSTRIDE;
        u64 w2a[4], w2b[4];
#pragma unroll
        for (int g = 0; g < 4; ++g) {
            w2a[g] = *(const u64*)(wr + g * 64 + n0);
            w2b[g] = *(const u64*)(wr + WSTRIDE + g * 64 + n0);
        }
#pragma unroll
        for (int j = 0; j < 8; ++j) {
            u64 sa = splat2(__shfl_sync(FULLMASK, src[0][j], h2));
#pragma unroll
            for (int g = 0; g < 4; ++g) acc[g][j] = fma2(sa, w2a[g], acc[g][j]);
        }
#pragma unroll
        for (int j = 0; j < 8; ++j) {
            u64 sb = splat2(__shfl_sync(FULLMASK, src[1][j], h2));
#pragma unroll
            for (int g = 0; g < 4; ++g) acc[g][j] = fma2(sb, w2b[g], acc[g][j]);
        }
    }
}

__global__ void __launch_bounds__(NT, 1)
snn_kernel(const float* __restrict__ x,
           const float* __restrict__ Wih1, const float* __restrict__ Whh1,
           const float* __restrict__ bih1, const float* __restrict__ bhh1,
           const float* __restrict__ thr1p,
           const float* __restrict__ Wih2, const float* __restrict__ Whh2,
           const float* __restrict__ bih2, const float* __restrict__ bhh2,
           const float* __restrict__ thr2p,
           const float* __restrict__ Wout, const float* __restrict__ bout,
           float* __restrict__ out) {
    extern __shared__ float sm[];
    const int tid  = threadIdx.x;
    const int lane = tid & 31;
    const int w    = tid >> 5;
    const int n0   = lane << 1;          // this lane's neuron pair
    const int bl   = w << 3;             // local batch base (8 per warp)
    const int cta_b0 = blockIdx.x * 64;

    // ---- stage weights (transposed, stride 258 -> conflict-free reads) ----
    for (int i = tid; i < 256 * 64; i += NT) {
        int r = i >> 6, h = i & 63;
        sm[OFF_W1T + h * WSTRIDE + r]        = Whh1[i];
        sm[OFF_W2T + h * WSTRIDE + r]        = Wih2[i];
        sm[OFF_W2T + (64 + h) * WSTRIDE + r] = Whh2[i];
    }
    if (tid < 256) {
        sm[OFF_WIH1 + tid] = Wih1[tid];
        sm[OFF_CB1 + tid]  = bih1[tid] + bhh1[tid];
        sm[OFF_CB2 + tid]  = bih2[tid] + bhh2[tid];
    }
    for (int i = tid; i < 3328; i += NT) sm[OFF_WOUT + i] = Wout[i];
    for (int i = tid; i < 64 * 24; i += NT) sm[OFF_XS + i] = x[cta_b0 * 24 + i];
    __syncthreads();

    const float thr1 = thr1p[0], thr2 = thr2p[0];

    // register-resident state: [neuron 0/1][batch j]
    float syn1[2][8], mem1[2][8], syn2[2][8], mem2[2][8], spk1[2][8];
#pragma unroll
    for (int n = 0; n < 2; ++n)
#pragma unroll
        for (int j = 0; j < 8; ++j)
            syn1[n][j] = mem1[n][j] = syn2[n][j] = mem2[n][j] = spk1[n][j] = 0.0f;

    float oa[8][2];
#pragma unroll
    for (int j = 0; j < 8; ++j) oa[j][0] = oa[j][1] = 0.0f;

    u64 acc[4][8];

#pragma unroll 1
    for (int t = 0; t < 25; ++t) {
        if (t < 24) {
            // ---- layer 1: gates = mem1 @ Whh1^T + x*Wih1 + b ----
#pragma unroll
            for (int g = 0; g < 4; ++g)
#pragma unroll
                for (int j = 0; j < 8; ++j) acc[g][j] = 0ull;
            gemm64(acc, sm + OFF_W1T, mem1, n0);
#pragma unroll
            for (int j = 0; j < 8; ++j) {
                float xv = sm[OFF_XS + (bl + j) * 24 + t];
                float2 gi = unpack2(acc[0][j]);
                float2 gf = unpack2(acc[1][j]);
                float2 gg = unpack2(acc[2][j]);
                float2 go = unpack2(acc[3][j]);
#pragma unroll
                for (int n = 0; n < 2; ++n) {
                    float Gi = (n ? gi.y : gi.x) + sm[OFF_CB1 + 0 * 64 + n0 + n]
                             + xv * sm[OFF_WIH1 + 0 * 64 + n0 + n];
                    float Gf = (n ? gf.y : gf.x) + sm[OFF_CB1 + 1 * 64 + n0 + n]
                             + xv * sm[OFF_WIH1 + 1 * 64 + n0 + n];
                    float Gg = (n ? gg.y : gg.x) + sm[OFF_CB1 + 2 * 64 + n0 + n]
                             + xv * sm[OFF_WIH1 + 2 * 64 + n0 + n];
                    float Go = (n ? go.y : go.x) + sm[OFF_CB1 + 3 * 64 + n0 + n]
                             + xv * sm[OFF_WIH1 + 3 * 64 + n0 + n];
                    cellpw(Gi, Gf, Gg, Go, syn1[n][j], mem1[n][j], spk1[n][j], thr1);
                }
            }
        }
        // ---- layer 2 ----
#pragma unroll
        for (int g = 0; g < 4; ++g)
#pragma unroll
            for (int j = 0; j < 8; ++j) acc[g][j] = 0ull;
        gemm64(acc, sm + OFF_W2T + 64 * WSTRIDE, mem2, n0);   // dense mem2 part
        if (t < 24) {
            // ---- SPARSE spk1 part: spk ∈ {0,1}; iterate firing neurons only.
            // Ballot bit l of m0 -> neuron 2l fired; of m1 -> neuron 2l+1.
            // Bit-exact vs dense: skipped terms are exact zeros, add == fma(1,.,.).
#pragma unroll 1
            for (int j = 0; j < 8; ++j) {
                unsigned m0 = __ballot_sync(FULLMASK, spk1[0][j] != 0.0f);
                unsigned m1 = __ballot_sync(FULLMASK, spk1[1][j] != 0.0f);
                while (m0) {
                    int h = __ffs(m0) - 1; m0 &= m0 - 1;
                    const float* wr = sm + OFF_W2T + (2 * h) * WSTRIDE + n0;
                    acc[0][j] = add2(acc[0][j], *(const u64*)(wr));
                    acc[1][j] = add2(acc[1][j], *(const u64*)(wr + 64));
                    acc[2][j] = add2(acc[2][j], *(const u64*)(wr + 128));
                    acc[3][j] = add2(acc[3][j], *(const u64*)(wr + 192));
                }
                while (m1) {
                    int h = __ffs(m1) - 1; m1 &= m1 - 1;
                    const float* wr = sm + OFF_W2T + (2 * h + 1) * WSTRIDE + n0;
                    acc[0][j] = add2(acc[0][j], *(const u64*)(wr));
                    acc[1][j] = add2(acc[1][j], *(const u64*)(wr + 64));
                    acc[2][j] = add2(acc[2][j], *(const u64*)(wr + 128));
                    acc[3][j] = add2(acc[3][j], *(const u64*)(wr + 192));
                }
            }
        } else {
            gemm64(acc, sm + OFF_W2T, mem1, n0);              // extra step: dense mem1
        }

        const int wcol = t * 64;
        const float wo00 = sm[OFF_WOUT + wcol + n0];
        const float wo01 = sm[OFF_WOUT + wcol + n0 + 1];
        const float wo10 = sm[OFF_WOUT + 1664 + wcol + n0];
        const float wo11 = sm[OFF_WOUT + 1664 + wcol + n0 + 1];
#pragma unroll
        for (int j = 0; j < 8; ++j) {
            float2 gi = unpack2(acc[0][j]);
            float2 gf = unpack2(acc[1][j]);
            float2 gg = unpack2(acc[2][j]);
            float2 go = unpack2(acc[3][j]);
#pragma unroll
            for (int n = 0; n < 2; ++n) {
                float Gi = (n ? gi.y : gi.x) + sm[OFF_CB2 + 0 * 64 + n0 + n];
                float Gf = (n ? gf.y : gf.x) + sm[OFF_CB2 + 1 * 64 + n0 + n];
                float Gg = (n ? gg.y : gg.x) + sm[OFF_CB2 + 2 * 64 + n0 + n];
                float Go = (n ? go.y : go.x) + sm[OFF_CB2 + 3 * 64 + n0 + n];
                float sp;
                cellpw(Gi, Gf, Gg, Go, syn2[n][j], mem2[n][j], sp, thr2);
                oa[j][0] += sp * (n ? wo01 : wo00);
                oa[j][1] += sp * (n ? wo11 : wo10);
            }
        }
    }

    // ---- final mem2 contribution (columns 25*64 .. 25*64+63) ----
#pragma unroll
    for (int n = 0; n < 2; ++n) {
        float wm0 = sm[OFF_WOUT + 25 * 64 + n0 + n];
        float wm1 = sm[OFF_WOUT + 1664 + 25 * 64 + n0 + n];
#pragma unroll
        for (int j = 0; j < 8; ++j) {
            oa[j][0] += mem2[n][j] * wm0;
            oa[j][1] += mem2[n][j] * wm1;
        }
    }

    // ---- warp reduction over the 32 neuron-owner lanes ----
#pragma unroll
    for (int j = 0; j < 8; ++j)
#pragma unroll
        for (int k = 0; k < 2; ++k) {
            float v = oa[j][k];
#pragma unroll
            for (int off = 16; off; off >>= 1)
                v += __shfl_xor_sync(FULLMASK, v, off);
            oa[j][k] = v;
        }

    if (lane < 16) {
        int j = lane >> 1, k = lane & 1;
        out[(cta_b0 + bl + j) * 2 + k] = oa[j][k] + bout[k];
    }
}

extern "C" void kernel_launch(void* const* d_in, const int* in_sizes, int n_in,
                              void* d_out, int out_size) {
    const float* x    = (const float*)d_in[0];
    const float* Wih1 = (const float*)d_in[1];
    const float* Whh1 = (const float*)d_in[2];
    const float* bih1 = (const float*)d_in[3];
    const float* bhh1 = (const float*)d_in[4];
    const float* thr1 = (const float*)d_in[5];
    const float* Wih2 = (const float*)d_in[6];
    const float* Whh2 = (const float*)d_in[7];
    const float* bih2 = (const float*)d_in[8];
    const float* bhh2 = (const float*)d_in[9];
    const float* thr2 = (const float*)d_in[10];
    const float* Wout = (const float*)d_in[11];
    const float* bout = (const float*)d_in[12];
    float* out = (float*)d_out;

    int B = in_sizes[0] / 24;  // 65536

    cudaFuncSetAttribute(snn_kernel,
                         cudaFuncAttributeMaxDynamicSharedMemorySize,
                         SMEM_BYTES);

    snn_kernel<<<B / 64, NT, SMEM_BYTES>>>(
        x, Wih1, Whh1, bih1, bhh1, thr1,
        Wih2, Whh2, bih2, bhh2, thr2, Wout, bout, out);
}

// round 17
// speedup vs baseline: 1.4773x; 1.2574x over previous
#include <cuda_runtime.h>

#define FULLMASK 0xffffffffu
#define WSTRIDE 258
#define NT 256

// ---- smem layout (float offsets) ----
#define OFF_W1T  0                      // [64][258]  Whh1^T
#define OFF_W2T  (64 * WSTRIDE)         // [128][258] rows 0..63 Wih2^T, 64..127 Whh2^T
#define OFF_WIH1 (OFF_W2T + 128 * WSTRIDE)
#define OFF_CB1  (OFF_WIH1 + 256)
#define OFF_CB2  (OFF_CB1 + 256)
#define OFF_WOUT (OFF_CB2 + 256)        // [2][1664]
#define OFF_XS   (OFF_WOUT + 3328)      // [64][24]
#define SMEM_FLOATS (OFF_XS + 64 * 24)
#define SMEM_BYTES  (SMEM_FLOATS * 4)   // 220672 B

typedef unsigned long long u64;

static __device__ __forceinline__ u64 splat2(float x) {
    u64 d; asm("mov.b64 %0, {%1, %1};" : "=l"(d) : "f"(x)); return d;
}
static __device__ __forceinline__ float2 unpack2(u64 v) {
    float lo, hi; asm("mov.b64 {%0, %1}, %2;" : "=f"(lo), "=f"(hi) : "l"(v));
    return make_float2(lo, hi);
}
static __device__ __forceinline__ u64 fma2(u64 a, u64 b, u64 c) {
    u64 d; asm("fma.rn.f32x2 %0, %1, %2, %3;" : "=l"(d) : "l"(a), "l"(b), "l"(c));
    return d;
}

// Fused SLSTM pointwise, 5 EX2 + 2 RCP (proven R4..R15, rel_err ~3e-8).
static __device__ __forceinline__ void cellpw(float Gi, float Gf, float Gg, float Go,
                                              float& syn, float& mem, float& spk,
                                              float thr) {
    float a = 1.0f + __expf(-Gi);
    float c = 1.0f + __expf(-Gf);
    float b = 1.0f + __expf(-2.0f * Gg);
    float ab = a * b;
    float r = __fdividef(1.0f, ab * c);
    float sn = (ab * syn + c * (2.0f - b)) * r;
    float p = 1.0f + __expf(-Go);
    float q = 1.0f + __expf(-2.0f * sn);
    float s = __fdividef(1.0f, p * q);
    float rst = (mem > thr) ? thr : 0.0f;
    float mn = s * (2.0f - q) - rst;
    syn = sn;
    mem = mn;
    spk = (mn > thr) ? 1.0f : 0.0f;
}

// Dense 64-row matvec (R3 layout): warp-uniform broadcast via shfl.
// Lane owns neuron pair n0=2*lane; src[n][j] = state of neuron 2*lane+n, batch j.
static __device__ __forceinline__ void gemm64(u64 (&acc)[4][8],
                                              const float* __restrict__ wbase,
                                              const float (&src)[2][8], int n0) {
#pragma unroll 2
    for (int h2 = 0; h2 < 32; ++h2) {
        const float* wr = wbase + (h2 * 2) * WSTRIDE;
        u64 w2a[4], w2b[4];
#pragma unroll
        for (int g = 0; g < 4; ++g) {
            w2a[g] = *(const u64*)(wr + g * 64 + n0);
            w2b[g] = *(const u64*)(wr + WSTRIDE + g * 64 + n0);
        }
#pragma unroll
        for (int j = 0; j < 8; ++j) {
            u64 sa = splat2(__shfl_sync(FULLMASK, src[0][j], h2));
#pragma unroll
            for (int g = 0; g < 4; ++g) acc[g][j] = fma2(sa, w2a[g], acc[g][j]);
        }
#pragma unroll
        for (int j = 0; j < 8; ++j) {
            u64 sb = splat2(__shfl_sync(FULLMASK, src[1][j], h2));
#pragma unroll
            for (int g = 0; g < 4; ++g) acc[g][j] = fma2(sb, w2b[g], acc[g][j]);
        }
    }
}

__global__ void __launch_bounds__(NT, 1)
snn_kernel(const float* __restrict__ x,
           const float* __restrict__ Wih1, const float* __restrict__ Whh1,
           const float* __restrict__ bih1, const float* __restrict__ bhh1,
           const float* __restrict__ thr1p,
           const float* __restrict__ Wih2, const float* __restrict__ Whh2,
           const float* __restrict__ bih2, const float* __restrict__ bhh2,
           const float* __restrict__ thr2p,
           const float* __restrict__ Wout, const float* __restrict__ bout,
           float* __restrict__ out) {
    extern __shared__ float sm[];
    const int tid  = threadIdx.x;
    const int lane = tid & 31;
    const int w    = tid >> 5;
    const int n0   = lane << 1;          // this lane's neuron pair
    const int bl   = w << 3;             // local batch base (8 per warp)
    const int cta_b0 = blockIdx.x * 64;

    // ---- stage weights (transposed, stride 258 -> conflict-free reads) ----
    for (int i = tid; i < 256 * 64; i += NT) {
        int r = i >> 6, h = i & 63;
        sm[OFF_W1T + h * WSTRIDE + r]        = Whh1[i];
        sm[OFF_W2T + h * WSTRIDE + r]        = Wih2[i];
        sm[OFF_W2T + (64 + h) * WSTRIDE + r] = Whh2[i];
    }
    if (tid < 256) {
        sm[OFF_WIH1 + tid] = Wih1[tid];
        sm[OFF_CB1 + tid]  = bih1[tid] + bhh1[tid];
        sm[OFF_CB2 + tid]  = bih2[tid] + bhh2[tid];
    }
    for (int i = tid; i < 3328; i += NT) sm[OFF_WOUT + i] = Wout[i];
    for (int i = tid; i < 64 * 24; i += NT) sm[OFF_XS + i] = x[cta_b0 * 24 + i];
    __syncthreads();

    const float thr1 = thr1p[0], thr2 = thr2p[0];

    // register-resident state: [neuron 0/1][batch j]
    float syn1[2][8], mem1[2][8], syn2[2][8], mem2[2][8], spk1[2][8];
#pragma unroll
    for (int n = 0; n < 2; ++n)
#pragma unroll
        for (int j = 0; j < 8; ++j)
            syn1[n][j] = mem1[n][j] = syn2[n][j] = mem2[n][j] = spk1[n][j] = 0.0f;

    float oa[8][2];
#pragma unroll
    for (int j = 0; j < 8; ++j) oa[j][0] = oa[j][1] = 0.0f;

    u64 acc[4][8];

#pragma unroll 1
    for (int t = 0; t < 25; ++t) {
        if (t < 24) {
            // ---- layer 1: gates = mem1 @ Whh1^T + x*Wih1 + b ----
#pragma unroll
            for (int g = 0; g < 4; ++g)
#pragma unroll
                for (int j = 0; j < 8; ++j) acc[g][j] = 0ull;
            gemm64(acc, sm + OFF_W1T, mem1, n0);
#pragma unroll
            for (int j = 0; j < 8; ++j) {
                float xv = sm[OFF_XS + (bl + j) * 24 + t];
                float2 gi = unpack2(acc[0][j]);
                float2 gf = unpack2(acc[1][j]);
                float2 gg = unpack2(acc[2][j]);
                float2 go = unpack2(acc[3][j]);
#pragma unroll
                for (int n = 0; n < 2; ++n) {
                    float Gi = (n ? gi.y : gi.x) + sm[OFF_CB1 + 0 * 64 + n0 + n]
                             + xv * sm[OFF_WIH1 + 0 * 64 + n0 + n];
                    float Gf = (n ? gf.y : gf.x) + sm[OFF_CB1 + 1 * 64 + n0 + n]
                             + xv * sm[OFF_WIH1 + 1 * 64 + n0 + n];
                    float Gg = (n ? gg.y : gg.x) + sm[OFF_CB1 + 2 * 64 + n0 + n]
                             + xv * sm[OFF_WIH1 + 2 * 64 + n0 + n];
                    float Go = (n ? go.y : go.x) + sm[OFF_CB1 + 3 * 64 + n0 + n]
                             + xv * sm[OFF_WIH1 + 3 * 64 + n0 + n];
                    cellpw(Gi, Gf, Gg, Go, syn1[n][j], mem1[n][j], spk1[n][j], thr1);
                }
            }
        }
        // ---- layer 2 ----
#pragma unroll
        for (int g = 0; g < 4; ++g)
#pragma unroll
            for (int j = 0; j < 8; ++j) acc[g][j] = 0ull;
        gemm64(acc, sm + OFF_W2T + 64 * WSTRIDE, mem2, n0);   // dense mem2 part
        if (t < 24) {
            // ---- SPARSE spk1 part, union-mask row loop.
            // mA bit l: some batch fired neuron 2l; mB: neuron 2l+1.
            // Per firing row: load once, fma all 8 batches (spk is exactly 0/1
            // -> fma2(0,w,acc)==acc, bit-exact vs dense).
            unsigned mA = 0, mB = 0;
#pragma unroll
            for (int j = 0; j < 8; ++j) {
                mA |= __ballot_sync(FULLMASK, spk1[0][j] != 0.0f);
                mB |= __ballot_sync(FULLMASK, spk1[1][j] != 0.0f);
            }
            while (mA) {
                int h = __ffs(mA) - 1; mA &= mA - 1;
                const float* wr = sm + OFF_W2T + (2 * h) * WSTRIDE + n0;
                u64 w0 = *(const u64*)(wr);
                u64 w1 = *(const u64*)(wr + 64);
                u64 w2 = *(const u64*)(wr + 128);
                u64 w3 = *(const u64*)(wr + 192);
#pragma unroll
                for (int j = 0; j < 8; ++j) {
                    u64 s = splat2(__shfl_sync(FULLMASK, spk1[0][j], h));
                    acc[0][j] = fma2(s, w0, acc[0][j]);
                    acc[1][j] = fma2(s, w1, acc[1][j]);
                    acc[2][j] = fma2(s, w2, acc[2][j]);
                    acc[3][j] = fma2(s, w3, acc[3][j]);
                }
            }
            while (mB) {
                int h = __ffs(mB) - 1; mB &= mB - 1;
                const float* wr = sm + OFF_W2T + (2 * h + 1) * WSTRIDE + n0;
                u64 w0 = *(const u64*)(wr);
                u64 w1 = *(const u64*)(wr + 64);
                u64 w2 = *(const u64*)(wr + 128);
                u64 w3 = *(const u64*)(wr + 192);
#pragma unroll
                for (int j = 0; j < 8; ++j) {
                    u64 s = splat2(__shfl_sync(FULLMASK, spk1[1][j], h));
                    acc[0][j] = fma2(s, w0, acc[0][j]);
                    acc[1][j] = fma2(s, w1, acc[1][j]);
                    acc[2][j] = fma2(s, w2, acc[2][j]);
                    acc[3][j] = fma2(s, w3, acc[3][j]);
                }
            }
        } else {
            gemm64(acc, sm + OFF_W2T, mem1, n0);              // extra step: dense mem1
        }

        const int wcol = t * 64;
        const float wo00 = sm[OFF_WOUT + wcol + n0];
        const float wo01 = sm[OFF_WOUT + wcol + n0 + 1];
        const float wo10 = sm[OFF_WOUT + 1664 + wcol + n0];
        const float wo11 = sm[OFF_WOUT + 1664 + wcol + n0 + 1];
#pragma unroll
        for (int j = 0; j < 8; ++j) {
            float2 gi = unpack2(acc[0][j]);
            float2 gf = unpack2(acc[1][j]);
            float2 gg = unpack2(acc[2][j]);
            float2 go = unpack2(acc[3][j]);
#pragma unroll
            for (int n = 0; n < 2; ++n) {
                float Gi = (n ? gi.y : gi.x) + sm[OFF_CB2 + 0 * 64 + n0 + n];
                float Gf = (n ? gf.y : gf.x) + sm[OFF_CB2 + 1 * 64 + n0 + n];
                float Gg = (n ? gg.y : gg.x) + sm[OFF_CB2 + 2 * 64 + n0 + n];
                float Go = (n ? go.y : go.x) + sm[OFF_CB2 + 3 * 64 + n0 + n];
                float sp;
                cellpw(Gi, Gf, Gg, Go, syn2[n][j], mem2[n][j], sp, thr2);
                oa[j][0] += sp * (n ? wo01 : wo00);
                oa[j][1] += sp * (n ? wo11 : wo10);
            }
        }
    }

    // ---- final mem2 contribution (columns 25*64 .. 25*64+63) ----
#pragma unroll
    for (int n = 0; n < 2; ++n) {
        float wm0 = sm[OFF_WOUT + 25 * 64 + n0 + n];
        float wm1 = sm[OFF_WOUT + 1664 + 25 * 64 + n0 + n];
#pragma unroll
        for (int j = 0; j < 8; ++j) {
            oa[j][0] += mem2[n][j] * wm0;
            oa[j][1] += mem2[n][j] * wm1;
        }
    }

    // ---- warp reduction over the 32 neuron-owner lanes ----
#pragma unroll
    for (int j = 0; j < 8; ++j)
#pragma unroll
        for (int k = 0; k < 2; ++k) {
            float v = oa[j][k];
#pragma unroll
            for (int off = 16; off; off >>= 1)
                v += __shfl_xor_sync(FULLMASK, v, off);
            oa[j][k] = v;
        }

    if (lane < 16) {
        int j = lane >> 1, k = lane & 1;
        out[(cta_b0 + bl + j) * 2 + k] = oa[j][k] + bout[k];
    }
}

extern "C" void kernel_launch(void* const* d_in, const int* in_sizes, int n_in,
                              void* d_out, int out_size) {
    const float* x    = (const float*)d_in[0];
    const float* Wih1 = (const float*)d_in[1];
    const float* Whh1 = (const float*)d_in[2];
    const float* bih1 = (const float*)d_in[3];
    const float* bhh1 = (const float*)d_in[4];
    const float* thr1 = (const float*)d_in[5];
    const float* Wih2 = (const float*)d_in[6];
    const float* Whh2 = (const float*)d_in[7];
    const float* bih2 = (const float*)d_in[8];
    const float* bhh2 = (const float*)d_in[9];
    const float* thr2 = (const float*)d_in[10];
    const float* Wout = (const float*)d_in[11];
    const float* bout = (const float*)d_in[12];
    float* out = (float*)d_out;

    int B = in_sizes[0] / 24;  // 65536

    cudaFuncSetAttribute(snn_kernel,
                         cudaFuncAttributeMaxDynamicSharedMemorySize,
                         SMEM_BYTES);

    snn_kernel<<<B / 64, NT, SMEM_BYTES>>>(
        x, Wih1, Whh1, bih1, bhh1, thr1,
        Wih2, Whh2, bih2, bhh2, thr2, Wout, bout, out);
}